// round 1
// baseline (speedup 1.0000x reference)
#include <cuda_runtime.h>
#include <math.h>

#define SEQ 2048
#define DM  1024
#define NH  16
#define DK  64

// Scratch (device globals — no allocation allowed)
__device__ float g_Q[SEQ * DM];
__device__ float g_K[SEQ * DM];
__device__ float g_V[SEQ * DM];
__device__ float g_C[SEQ * DM];

// ---------------------------------------------------------------------------
// NT SGEMM: C[M,N] = alpha * A[M,K] * B[N,K]^T (+ bias[col])
// Tiles: 128x128, BK=8, 256 threads, 8x8 per-thread microtile.
// M,N implied by gridDim (y=M/128, x=N/128). blockIdx.z batches via strides.
// ---------------------------------------------------------------------------
__global__ __launch_bounds__(256)
void sgemm_nt_128(const float* __restrict__ A,
                  const float* __restrict__ B,
                  float* __restrict__ C,
                  int K, int lda, int ldb, int ldc,
                  float alpha,
                  const float* __restrict__ bias,
                  long long sAz, long long sBz, long long sCz)
{
    A += (long long)blockIdx.z * sAz;
    B += (long long)blockIdx.z * sBz;
    C += (long long)blockIdx.z * sCz;

    __shared__ __align__(16) float As[8][128];
    __shared__ __align__(16) float Bs[8][128];

    const int t    = threadIdx.x;
    const int tx   = t & 15;        // N microtile index (x8)
    const int ty   = t >> 4;        // M microtile index (x8)
    const int lrow = t >> 1;        // 0..127 loader row
    const int lcol = (t & 1) * 4;   // 0 or 4 loader col

    const float* Ap = A + (long long)(blockIdx.y * 128 + lrow) * lda + lcol;
    const float* Bp = B + (long long)(blockIdx.x * 128 + lrow) * ldb + lcol;

    float acc[8][8];
#pragma unroll
    for (int i = 0; i < 8; i++)
#pragma unroll
        for (int j = 0; j < 8; j++) acc[i][j] = 0.f;

    for (int k0 = 0; k0 < K; k0 += 8) {
        float4 a = *(const float4*)(Ap + k0);
        float4 b = *(const float4*)(Bp + k0);
        As[lcol + 0][lrow] = a.x; As[lcol + 1][lrow] = a.y;
        As[lcol + 2][lrow] = a.z; As[lcol + 3][lrow] = a.w;
        Bs[lcol + 0][lrow] = b.x; Bs[lcol + 1][lrow] = b.y;
        Bs[lcol + 2][lrow] = b.z; Bs[lcol + 3][lrow] = b.w;
        __syncthreads();
#pragma unroll
        for (int kk = 0; kk < 8; ++kk) {
            float ra[8], rb[8];
#pragma unroll
            for (int i = 0; i < 8; i++) ra[i] = As[kk][ty * 8 + i];
#pragma unroll
            for (int j = 0; j < 8; j++) rb[j] = Bs[kk][tx * 8 + j];
#pragma unroll
            for (int i = 0; i < 8; i++)
#pragma unroll
                for (int j = 0; j < 8; j++)
                    acc[i][j] = fmaf(ra[i], rb[j], acc[i][j]);
        }
        __syncthreads();
    }

#pragma unroll
    for (int i = 0; i < 8; i++) {
        int row = blockIdx.y * 128 + ty * 8 + i;
#pragma unroll
        for (int j = 0; j < 8; j += 4) {
            int col = blockIdx.x * 128 + tx * 8 + j;
            float4 o;
            o.x = alpha * acc[i][j + 0] + (bias ? bias[col + 0] : 0.f);
            o.y = alpha * acc[i][j + 1] + (bias ? bias[col + 1] : 0.f);
            o.z = alpha * acc[i][j + 2] + (bias ? bias[col + 2] : 0.f);
            o.w = alpha * acc[i][j + 3] + (bias ? bias[col + 3] : 0.f);
            *(float4*)(&C[(long long)row * ldc + col]) = o;
        }
    }
}

// ---------------------------------------------------------------------------
// NN SGEMM: C[M,64] = A[M,K] * B[K,64]
// Tiles: 128x64, BK=16, 256 threads, 8x4 per-thread microtile.
// Used for ctx = attn @ V (per head). gridDim: x=1, y=M/128, z=heads.
// ---------------------------------------------------------------------------
__global__ __launch_bounds__(256)
void sgemm_nn_128x64(const float* __restrict__ A,
                     const float* __restrict__ B,
                     float* __restrict__ C,
                     int K, int lda, int ldb, int ldc,
                     long long sAz, long long sBz, long long sCz)
{
    A += (long long)blockIdx.z * sAz;
    B += (long long)blockIdx.z * sBz;
    C += (long long)blockIdx.z * sCz;

    __shared__ __align__(16) float As[16][128];
    __shared__ __align__(16) float Bs[16][64];

    const int t    = threadIdx.x;
    const int tx   = t & 15;        // N microtile (x4)
    const int ty   = t >> 4;        // M microtile (x8)
    const int arow = t >> 1;        // 0..127
    const int acol = (t & 1) * 8;   // 0 or 8
    const int brow = t >> 4;        // 0..15
    const int bcol = (t & 15) * 4;  // 0..60

    const float* Ap = A + (long long)(blockIdx.y * 128 + arow) * lda + acol;
    const float* Bp = B + (long long)brow * ldb + bcol;

    float acc[8][4];
#pragma unroll
    for (int i = 0; i < 8; i++)
#pragma unroll
        for (int j = 0; j < 4; j++) acc[i][j] = 0.f;

    for (int k0 = 0; k0 < K; k0 += 16) {
        float4 a0 = *(const float4*)(Ap + k0);
        float4 a1 = *(const float4*)(Ap + k0 + 4);
        As[acol + 0][arow] = a0.x; As[acol + 1][arow] = a0.y;
        As[acol + 2][arow] = a0.z; As[acol + 3][arow] = a0.w;
        As[acol + 4][arow] = a1.x; As[acol + 5][arow] = a1.y;
        As[acol + 6][arow] = a1.z; As[acol + 7][arow] = a1.w;
        float4 b = *(const float4*)(Bp + (long long)k0 * ldb);
        *(float4*)(&Bs[brow][bcol]) = b;
        __syncthreads();
#pragma unroll
        for (int kk = 0; kk < 16; ++kk) {
            float ra[8], rb[4];
#pragma unroll
            for (int i = 0; i < 8; i++) ra[i] = As[kk][ty * 8 + i];
#pragma unroll
            for (int j = 0; j < 4; j++) rb[j] = Bs[kk][tx * 4 + j];
#pragma unroll
            for (int i = 0; i < 8; i++)
#pragma unroll
                for (int j = 0; j < 4; j++)
                    acc[i][j] = fmaf(ra[i], rb[j], acc[i][j]);
        }
        __syncthreads();
    }

#pragma unroll
    for (int i = 0; i < 8; i++) {
        int row = blockIdx.y * 128 + ty * 8 + i;
        int col = tx * 4;
        float4 o = make_float4(acc[i][0], acc[i][1], acc[i][2], acc[i][3]);
        *(float4*)(&C[(long long)row * ldc + col]) = o;
    }
}

// ---------------------------------------------------------------------------
// RoPE (in-place on Q and K): per (s, h, i<32):
//   q[i]    = q[i]*cos - q[i+32]*sin
//   q[i+32] = q[i+32]*cos + q[i]*sin,  angle = s * 10000^(-i/32)
// ---------------------------------------------------------------------------
__global__ void rope_kernel(float* __restrict__ Q, float* __restrict__ K)
{
    int tid = blockIdx.x * blockDim.x + threadIdx.x;
    if (tid >= SEQ * NH * 32) return;
    int i = tid & 31;
    int h = (tid >> 5) & (NH - 1);
    int s = tid >> 9;

    // ln(10000)/32 = 0.28782313662425576
    float inv_freq = expf(-0.28782313662425576f * (float)i);
    float angle = (float)s * inv_freq;
    float sn, cs;
    sincosf(angle, &sn, &cs);

    long long base = (long long)s * DM + h * DK + i;
    float q1 = Q[base], q2 = Q[base + 32];
    Q[base]      = q1 * cs - q2 * sn;
    Q[base + 32] = q2 * cs + q1 * sn;
    float k1 = K[base], k2 = K[base + 32];
    K[base]      = k1 * cs - k2 * sn;
    K[base + 32] = k2 * cs + k1 * sn;
}

// ---------------------------------------------------------------------------
// Row softmax in-place: one block (256 threads) per row of length 2048.
// ---------------------------------------------------------------------------
__global__ __launch_bounds__(256)
void softmax_rows(float* __restrict__ A)
{
    float* p = A + (long long)blockIdx.x * 2048;
    const int t = threadIdx.x;
    const int lane = t & 31, w = t >> 5;

    float v[8];
    float m = -INFINITY;
#pragma unroll
    for (int j = 0; j < 8; j++) { v[j] = p[t + j * 256]; m = fmaxf(m, v[j]); }

    __shared__ float shm[8];
    __shared__ float shs[8];
#pragma unroll
    for (int o = 16; o; o >>= 1) m = fmaxf(m, __shfl_xor_sync(0xffffffffu, m, o));
    if (lane == 0) shm[w] = m;
    __syncthreads();
    float mm = shm[0];
#pragma unroll
    for (int i = 1; i < 8; i++) mm = fmaxf(mm, shm[i]);

    float sum = 0.f;
#pragma unroll
    for (int j = 0; j < 8; j++) { v[j] = expf(v[j] - mm); sum += v[j]; }
#pragma unroll
    for (int o = 16; o; o >>= 1) sum += __shfl_xor_sync(0xffffffffu, sum, o);
    if (lane == 0) shs[w] = sum;
    __syncthreads();
    float tot = 0.f;
#pragma unroll
    for (int i = 0; i < 8; i++) tot += shs[i];
    float inv = 1.0f / tot;
#pragma unroll
    for (int j = 0; j < 8; j++) p[t + j * 256] = v[j] * inv;
}

// ---------------------------------------------------------------------------
extern "C" void kernel_launch(void* const* d_in, const int* in_sizes, int n_in,
                              void* d_out, int out_size)
{
    const float* q  = (const float*)d_in[0];
    const float* k  = (const float*)d_in[1];
    const float* v  = (const float*)d_in[2];
    const float* wq = (const float*)d_in[3];
    const float* wk = (const float*)d_in[4];
    const float* wv = (const float*)d_in[5];
    const float* wo = (const float*)d_in[6];
    const float* bo = (const float*)d_in[7];

    float* out  = (float*)d_out;                        // [2048, 1024]
    float* attn = out + (size_t)SEQ * DM;               // [16, 2048, 2048]

    float *pQ, *pK, *pV, *pC;
    cudaGetSymbolAddress((void**)&pQ, g_Q);
    cudaGetSymbolAddress((void**)&pK, g_K);
    cudaGetSymbolAddress((void**)&pV, g_V);
    cudaGetSymbolAddress((void**)&pC, g_C);

    // 1) Projections: X @ W^T  (M=2048, N=1024, K=1024)
    dim3 gProj(DM / 128, SEQ / 128, 1);
    sgemm_nt_128<<<gProj, 256>>>(q, wq, pQ, DM, DM, DM, DM, 1.f, nullptr, 0, 0, 0);
    sgemm_nt_128<<<gProj, 256>>>(k, wk, pK, DM, DM, DM, DM, 1.f, nullptr, 0, 0, 0);
    sgemm_nt_128<<<gProj, 256>>>(v, wv, pV, DM, DM, DM, DM, 1.f, nullptr, 0, 0, 0);

    // 2) RoPE on Q, K (in-place)
    rope_kernel<<<(SEQ * NH * 32 + 255) / 256, 256>>>(pQ, pK);

    // 3) Scores: attn_h = (Q_h @ K_h^T) / 8   (M=N=2048, K=64, per head)
    dim3 gScore(SEQ / 128, SEQ / 128, NH);
    sgemm_nt_128<<<gScore, 256>>>(pQ, pK, attn, DK, DM, DM, SEQ, 0.125f, nullptr,
                                  DK, DK, (long long)SEQ * SEQ);

    // 4) Softmax in-place over each of the 16*2048 rows
    softmax_rows<<<NH * SEQ, 256>>>(attn);

    // 5) ctx_h = attn_h @ V_h   (M=2048, N=64, K=2048, per head)
    dim3 gAV(1, SEQ / 128, NH);
    sgemm_nn_128x64<<<gAV, 256>>>(attn, pV, pC, SEQ, SEQ, DM, DM,
                                  (long long)SEQ * SEQ, DK, DK);

    // 6) out = ctx @ w_o^T + b_o  (M=2048, N=1024, K=1024)
    sgemm_nt_128<<<gProj, 256>>>(pC, wo, out, DM, DM, DM, DM, 1.f, bo, 0, 0, 0);
}

// round 4
// speedup vs baseline: 1.7880x; 1.7880x over previous
#include <cuda_runtime.h>
#include <cuda_bf16.h>
#include <cstdint>
#include <math.h>

#define SEQ 2048
#define DM  1024
#define NH  16
#define DK  64

// Scratch (device globals — no allocation allowed)
__device__ float g_Q[SEQ * DM];
__device__ float g_K[SEQ * DM];
__device__ float g_V[SEQ * DM];
__device__ float g_C[SEQ * DM];

// ---------------------------------------------------------------------------
// bf16x2 pack with round-to-nearest: lo half = x0, hi half = x1
// ---------------------------------------------------------------------------
__device__ __forceinline__ uint32_t pack2_rn(float x0, float x1) {
    uint32_t r;
    asm("cvt.rn.bf16x2.f32 %0, %1, %2;" : "=r"(r) : "f"(x1), "f"(x0));
    return r;
}

// Convert pair to split (hi, lo) packed bf16x2 words.
__device__ __forceinline__ void cvt_split(float x0, float x1,
                                          uint32_t& ph, uint32_t& pl) {
    ph = pack2_rn(x0, x1);
    float h0 = __uint_as_float(ph << 16);
    float h1 = __uint_as_float(ph & 0xFFFF0000u);
    pl = pack2_rn(x0 - h0, x1 - h1);
}

// m16n8k16 bf16 mma, fp32 accumulate
__device__ __forceinline__ void mma16816(float* c, uint32_t a0, uint32_t a1,
                                         uint32_t a2, uint32_t a3,
                                         uint32_t b0, uint32_t b1) {
    asm volatile(
        "mma.sync.aligned.m16n8k16.row.col.f32.bf16.bf16.f32 "
        "{%0,%1,%2,%3},{%4,%5,%6,%7},{%8,%9},{%0,%1,%2,%3};"
        : "+f"(c[0]), "+f"(c[1]), "+f"(c[2]), "+f"(c[3])
        : "r"(a0), "r"(a1), "r"(a2), "r"(a3), "r"(b0), "r"(b1));
}

// ---------------------------------------------------------------------------
// Split-bf16 GEMM (near-fp32 accuracy):
//   NT=true : C[M,N] = alpha * A[M,K] * B[N,K]^T (+bias)
//   NT=false: C[M,N] = alpha * A[M,K] * B[K,N]   (+bias)
// Block tile 128x64, BK=16, 256 threads (8 warps, 32x32 warp tile),
// double-buffered SMEM. blockIdx.z batches via element strides sAz/sBz/sCz.
// ---------------------------------------------------------------------------
#define PA 136   // As row pitch (words): (136*k2+m)%32 = (8k2+m)%32 conflict-free
#define PB 72    // Bs row pitch (words): (72*k2+n)%32 = (8k2+n)%32 conflict-free

template <bool NT, bool HB>
__global__ __launch_bounds__(256, 2)
void gemm_split(const float* __restrict__ A, const float* __restrict__ B,
                float* __restrict__ C, int K, int lda, int ldb, int ldc,
                float alpha, const float* __restrict__ bias,
                long long sAz, long long sBz, long long sCz)
{
    A += (long long)blockIdx.z * sAz;
    B += (long long)blockIdx.z * sBz;
    C += (long long)blockIdx.z * sCz;

    __shared__ uint32_t AsH[2][8 * PA];
    __shared__ uint32_t AsL[2][8 * PA];
    __shared__ uint32_t BsH[2][8 * PB];
    __shared__ uint32_t BsL[2][8 * PB];

    const int t    = threadIdx.x;
    const int lane = t & 31, w = t >> 5;
    const int wm = w & 3;            // M warp (x32 rows)
    const int wn = w >> 2;           // N warp (x32 cols)
    const int grp = lane >> 2, qid = lane & 3;

    // --- loader indices ---
    const int lm  = t >> 1;       // A row within tile (0..127)
    const int lkp = t & 1;        // k half (0 or 1 -> k offset 0/8)
    const float* Ap = A + (long long)(blockIdx.y * 128 + lm) * lda + lkp * 8;

    const float* Bp;
    int bk2 = 0, bn = 0;
    if (NT) {
        // B rows are n (tile 64): only t<128 participate, n = t>>1 in 0..63
        Bp = B + (long long)(blockIdx.x * 64 + lm) * ldb + lkp * 8;
    } else {
        bk2 = t & 7;                // k-pair index 0..7
        bn  = ((t >> 3) & 15) * 4;  // n 0..60 step 4 (t<128)
        Bp  = B + (long long)(2 * bk2) * ldb + blockIdx.x * 64 + bn;
    }

    float acc[2][4][4];
#pragma unroll
    for (int i = 0; i < 2; i++)
#pragma unroll
        for (int j = 0; j < 4; j++)
#pragma unroll
            for (int r = 0; r < 4; r++) acc[i][j][r] = 0.f;

    float xa[8], xb[8];

    auto gload = [&](int k0) {
        *(float4*)&xa[0] = *(const float4*)(Ap + k0);
        *(float4*)&xa[4] = *(const float4*)(Ap + k0 + 4);
        if (t < 128) {
            if (NT) {
                *(float4*)&xb[0] = *(const float4*)(Bp + k0);
                *(float4*)&xb[4] = *(const float4*)(Bp + k0 + 4);
            } else {
                *(float4*)&xb[0] = *(const float4*)(Bp + (long long)k0 * ldb);
                *(float4*)&xb[4] = *(const float4*)(Bp + (long long)(k0 + 1) * ldb);
            }
        }
    };

    auto stage = [&](int buf) {
#pragma unroll
        for (int j = 0; j < 4; j++) {
            int k2 = lkp * 4 + j;
            uint32_t ph, pl;
            cvt_split(xa[2 * j], xa[2 * j + 1], ph, pl);
            AsH[buf][k2 * PA + lm] = ph;
            AsL[buf][k2 * PA + lm] = pl;
        }
        if (t < 128) {
            if (NT) {
#pragma unroll
                for (int j = 0; j < 4; j++) {
                    int k2 = lkp * 4 + j;
                    uint32_t ph, pl;
                    cvt_split(xb[2 * j], xb[2 * j + 1], ph, pl);
                    BsH[buf][k2 * PB + lm] = ph;
                    BsL[buf][k2 * PB + lm] = pl;
                }
            } else {
                uint32_t ph[4], pl[4];
#pragma unroll
                for (int j = 0; j < 4; j++)
                    cvt_split(xb[j], xb[4 + j], ph[j], pl[j]);
                *(uint4*)&BsH[buf][bk2 * PB + bn] = *(uint4*)ph;
                *(uint4*)&BsL[buf][bk2 * PB + bn] = *(uint4*)pl;
            }
        }
    };

    gload(0);
    stage(0);
    __syncthreads();

    for (int k0 = 0; k0 < K; k0 += 16) {
        const int buf = (k0 >> 4) & 1;
        const bool nxt = (k0 + 16) < K;
        if (nxt) gload(k0 + 16);

        // --- compute on buf ---
        uint32_t ah[2][4], al[2][4];
        const int rbase = wm * 32 + grp;
#pragma unroll
        for (int mt = 0; mt < 2; mt++) {
            int r0 = rbase + 16 * mt, r1 = r0 + 8;
            ah[mt][0] = AsH[buf][qid * PA + r0];
            ah[mt][1] = AsH[buf][qid * PA + r1];
            ah[mt][2] = AsH[buf][(qid + 4) * PA + r0];
            ah[mt][3] = AsH[buf][(qid + 4) * PA + r1];
            al[mt][0] = AsL[buf][qid * PA + r0];
            al[mt][1] = AsL[buf][qid * PA + r1];
            al[mt][2] = AsL[buf][(qid + 4) * PA + r0];
            al[mt][3] = AsL[buf][(qid + 4) * PA + r1];
        }
        const int cbase = wn * 32 + grp;
#pragma unroll
        for (int nt4 = 0; nt4 < 4; nt4++) {
            int ci = cbase + nt4 * 8;
            uint32_t bh0 = BsH[buf][qid * PB + ci];
            uint32_t bh1 = BsH[buf][(qid + 4) * PB + ci];
            uint32_t bl0 = BsL[buf][qid * PB + ci];
            uint32_t bl1 = BsL[buf][(qid + 4) * PB + ci];
#pragma unroll
            for (int mt = 0; mt < 2; mt++) {
                mma16816(acc[mt][nt4], ah[mt][0], ah[mt][1], ah[mt][2], ah[mt][3], bh0, bh1);
                mma16816(acc[mt][nt4], ah[mt][0], ah[mt][1], ah[mt][2], ah[mt][3], bl0, bl1);
                mma16816(acc[mt][nt4], al[mt][0], al[mt][1], al[mt][2], al[mt][3], bh0, bh1);
            }
        }

        if (nxt) stage(buf ^ 1);
        __syncthreads();
    }

    // --- epilogue ---
#pragma unroll
    for (int mt = 0; mt < 2; mt++) {
        int r0 = blockIdx.y * 128 + wm * 32 + 16 * mt + grp;
        int r1 = r0 + 8;
#pragma unroll
        for (int nt4 = 0; nt4 < 4; nt4++) {
            int col = blockIdx.x * 64 + wn * 32 + nt4 * 8 + 2 * qid;
            float b0 = HB ? bias[col] : 0.f;
            float b1 = HB ? bias[col + 1] : 0.f;
            float2 v0 = make_float2(alpha * acc[mt][nt4][0] + b0,
                                    alpha * acc[mt][nt4][1] + b1);
            float2 v1 = make_float2(alpha * acc[mt][nt4][2] + b0,
                                    alpha * acc[mt][nt4][3] + b1);
            *(float2*)&C[(long long)r0 * ldc + col] = v0;
            *(float2*)&C[(long long)r1 * ldc + col] = v1;
        }
    }
}

// ---------------------------------------------------------------------------
// RoPE (in-place on Q and K)
// ---------------------------------------------------------------------------
__global__ void rope_kernel(float* __restrict__ Q, float* __restrict__ K)
{
    int tid = blockIdx.x * blockDim.x + threadIdx.x;
    if (tid >= SEQ * NH * 32) return;
    int i = tid & 31;
    int h = (tid >> 5) & (NH - 1);
    int s = tid >> 9;

    float inv_freq = expf(-0.28782313662425576f * (float)i);
    float angle = (float)s * inv_freq;
    float sn, cs;
    sincosf(angle, &sn, &cs);

    long long base = (long long)s * DM + h * DK + i;
    float q1 = Q[base], q2 = Q[base + 32];
    Q[base]      = q1 * cs - q2 * sn;
    Q[base + 32] = q2 * cs + q1 * sn;
    float k1 = K[base], k2 = K[base + 32];
    K[base]      = k1 * cs - k2 * sn;
    K[base + 32] = k2 * cs + k1 * sn;
}

// ---------------------------------------------------------------------------
// Row softmax in-place: one block (256 threads) per row of length 2048.
// ---------------------------------------------------------------------------
__global__ __launch_bounds__(256)
void softmax_rows(float* __restrict__ A)
{
    float* p = A + (long long)blockIdx.x * 2048;
    const int t = threadIdx.x;
    const int lane = t & 31, w = t >> 5;

    float v[8];
    float m = -INFINITY;
#pragma unroll
    for (int j = 0; j < 8; j++) { v[j] = p[t + j * 256]; m = fmaxf(m, v[j]); }

    __shared__ float shm[8];
    __shared__ float shs[8];
#pragma unroll
    for (int o = 16; o; o >>= 1) m = fmaxf(m, __shfl_xor_sync(0xffffffffu, m, o));
    if (lane == 0) shm[w] = m;
    __syncthreads();
    float mm = shm[0];
#pragma unroll
    for (int i = 1; i < 8; i++) mm = fmaxf(mm, shm[i]);

    float sum = 0.f;
#pragma unroll
    for (int j = 0; j < 8; j++) { v[j] = expf(v[j] - mm); sum += v[j]; }
#pragma unroll
    for (int o = 16; o; o >>= 1) sum += __shfl_xor_sync(0xffffffffu, sum, o);
    if (lane == 0) shs[w] = sum;
    __syncthreads();
    float tot = 0.f;
#pragma unroll
    for (int i = 0; i < 8; i++) tot += shs[i];
    float inv = 1.0f / tot;
#pragma unroll
    for (int j = 0; j < 8; j++) p[t + j * 256] = v[j] * inv;
}

// ---------------------------------------------------------------------------
extern "C" void kernel_launch(void* const* d_in, const int* in_sizes, int n_in,
                              void* d_out, int out_size)
{
    const float* q  = (const float*)d_in[0];
    const float* k  = (const float*)d_in[1];
    const float* v  = (const float*)d_in[2];
    const float* wq = (const float*)d_in[3];
    const float* wk = (const float*)d_in[4];
    const float* wv = (const float*)d_in[5];
    const float* wo = (const float*)d_in[6];
    const float* bo = (const float*)d_in[7];

    float* out  = (float*)d_out;              // [2048, 1024]
    float* attn = out + (size_t)SEQ * DM;     // [16, 2048, 2048]

    float *pQ, *pK, *pV, *pC;
    cudaGetSymbolAddress((void**)&pQ, g_Q);
    cudaGetSymbolAddress((void**)&pK, g_K);
    cudaGetSymbolAddress((void**)&pV, g_V);
    cudaGetSymbolAddress((void**)&pC, g_C);

    // 1) Projections: X @ W^T  (M=2048, N=1024, K=1024)
    dim3 gProj(DM / 64, SEQ / 128, 1);
    gemm_split<true, false><<<gProj, 256>>>(q, wq, pQ, DM, DM, DM, DM, 1.f, nullptr, 0, 0, 0);
    gemm_split<true, false><<<gProj, 256>>>(k, wk, pK, DM, DM, DM, DM, 1.f, nullptr, 0, 0, 0);
    gemm_split<true, false><<<gProj, 256>>>(v, wv, pV, DM, DM, DM, DM, 1.f, nullptr, 0, 0, 0);

    // 2) RoPE on Q, K (in-place)
    rope_kernel<<<(SEQ * NH * 32 + 255) / 256, 256>>>(pQ, pK);

    // 3) Scores: attn_h = (Q_h @ K_h^T) / 8   (per head)
    dim3 gScore(SEQ / 64, SEQ / 128, NH);
    gemm_split<true, false><<<gScore, 256>>>(pQ, pK, attn, DK, DM, DM, SEQ, 0.125f,
                                             nullptr, DK, DK, (long long)SEQ * SEQ);

    // 4) Softmax over each of the 16*2048 rows
    softmax_rows<<<NH * SEQ, 256>>>(attn);

    // 5) ctx_h = attn_h @ V_h   (M=2048, N=64, K=2048, per head)
    dim3 gAV(1, SEQ / 128, NH);
    gemm_split<false, false><<<gAV, 256>>>(attn, pV, pC, SEQ, SEQ, DM, DM, 1.f,
                                           nullptr, (long long)SEQ * SEQ, DK, DK);

    // 6) out = ctx @ w_o^T + b_o
    dim3 gOut(DM / 64, SEQ / 128, 1);
    gemm_split<true, true><<<gOut, 256>>>(pC, wo, out, DM, DM, DM, DM, 1.f, bo, 0, 0, 0);
}